// round 2
// baseline (speedup 1.0000x reference)
#include <cuda_runtime.h>

#define T_DATA 50000
#define SUB_NO 20
#define H_NO   16
#define T_NO   200
#define COS_NO 20
#define E_NO   1000
#define I_NO   200

#define PI_F 3.14159265358979f

// padded grouped-signal length per channel: 199 leading zeros + T + tail zeros
#define TPA (T_NO - 1 + T_DATA + 640)   // 50839

// ---------------- device scratch (static, no allocations) ----------------
__device__ float g_K[SUB_NO * H_NO * 2 * T_NO];   // K[o][c][tau], o = s*16+h   (512 KB)
__device__ float g_S[2 * SUB_NO * TPA];           // 40 channels, channel-major (~8.1 MB)
__device__ float g_P[SUB_NO * T_DATA];            // per-subunit root partials  (4 MB)

// ---------------- packed f32x2 helpers ----------------
typedef unsigned long long ull;

__device__ __forceinline__ void fma2(ull &d, ull a, ull b) {
    asm("fma.rn.f32x2 %0, %1, %2, %0;" : "+l"(d) : "l"(a), "l"(b));
}
__device__ __forceinline__ ull pack2(float lo, float hi) {
    ull r;
    asm("mov.b64 %0, {%1,%2};" : "=l"(r) : "f"(lo), "f"(hi));
    return r;
}
__device__ __forceinline__ float fold2(ull v) {
    float lo, hi;
    asm("mov.b64 {%0,%1}, %2;" : "=f"(lo), "=f"(hi) : "l"(v));
    return lo + hi;
}
__device__ __forceinline__ float leaky(float v) { return v > 0.f ? v : 0.01f * v; }

// ---------------- kernel 0: zero padded signal buffer ----------------
__global__ void k_zero() {
    const int n = 2 * SUB_NO * TPA;
    for (int i = blockIdx.x * blockDim.x + threadIdx.x; i < n; i += gridDim.x * blockDim.x)
        g_S[i] = 0.f;
}

// ---------------- kernel 1: temporal kernels from raised-cosine basis ----------------
// one block per (o, c); 200 threads = tau
__global__ void k_kern(const float* __restrict__ Wc, float* __restrict__ out, int out_size) {
    const int oc  = blockIdx.x;        // 0..639
    const int ch  = oc & 1;
    const int od  = oc >> 1;           // 0..319
    const int tau = threadIdx.x;       // 0..199
    const float raw = 5.0f * logf((float)tau + 1.0f);
    float acc = 0.f;
#pragma unroll
    for (int b = 0; b < COS_NO; b++) {
        const float phi = 1.57079632679f * (float)b;
        float v = 0.f;
        if (raw >= phi - PI_F && raw <= phi + PI_F)
            v = 0.5f * cosf(raw - phi) + 0.5f;
        acc += v * Wc[od * (2 * COS_NO) + ch * COS_NO + b];
    }
    g_K[od * 400 + ch * 200 + tau] = acc;
    // reference returns the time-FLIPPED kernel as second output
    if (out_size >= T_DATA + 320 * 400)
        out[T_DATA + od * 400 + ch * 200 + (T_NO - 1 - tau)] = acc;
}

// ---------------- kernel 2: synapse grouping GEMMs ----------------
// blockIdx.y = 0: S_e [T,1000] x C_e^T -> channels 2s ; =1: S_i [T,200] x C_i^T -> channels 2s+1
// 128 threads, BM=256 t, BK=40, thread tile 8t x 5s, k-pair-packed f32x2 accumulation.
__global__ void __launch_bounds__(128) k_group(const float* __restrict__ Se,
                                               const float* __restrict__ Si,
                                               const float* __restrict__ Ce,
                                               const float* __restrict__ Ci) {
    const int part = blockIdx.y;
    const float* __restrict__ A = part ? Si : Se;
    const float* __restrict__ C = part ? Ci : Ce;
    const int Kdim = part ? I_NO : E_NO;

    const int t0  = blockIdx.x * 256;
    const int tid = threadIdx.x;
    const int tx  = tid & 31;
    const int ty  = tid >> 5;          // 0..3 -> 5 subunits each

    __shared__ __align__(16) float sA[256 * 42];  // stride 42 -> f32x2 stride 21 (conflict-free)
    __shared__ __align__(16) float sB[20 * 42];

    ull acc[8][5];
#pragma unroll
    for (int m = 0; m < 8; m++)
#pragma unroll
        for (int n = 0; n < 5; n++) acc[m][n] = 0ull;

    for (int k0 = 0; k0 < Kdim; k0 += 40) {
        // load A tile (256 x 40) as float2, coalesced
        for (int idx = tid; idx < 256 * 20; idx += 128) {
            const int r = idx / 20, c2 = idx % 20;
            const int t = t0 + r;
            float2 v = make_float2(0.f, 0.f);
            if (t < T_DATA)
                v = *(const float2*)&A[(size_t)t * Kdim + k0 + c2 * 2];
            *(float2*)&sA[r * 42 + c2 * 2] = v;
        }
        // load C tile (20 x 40)
        for (int idx = tid; idx < 20 * 20; idx += 128) {
            const int r = idx / 20, c2 = idx % 20;
            *(float2*)&sB[r * 42 + c2 * 2] = *(const float2*)&C[(size_t)r * Kdim + k0 + c2 * 2];
        }
        __syncthreads();

#pragma unroll 4
        for (int kk = 0; kk < 20; kk++) {
            ull a2[8];
#pragma unroll
            for (int m = 0; m < 8; m++)
                a2[m] = *(const ull*)&sA[(tx + 32 * m) * 42 + 2 * kk];
#pragma unroll
            for (int n = 0; n < 5; n++) {
                const ull b2 = *(const ull*)&sB[(ty * 5 + n) * 42 + 2 * kk];
#pragma unroll
                for (int m = 0; m < 8; m++) fma2(acc[m][n], a2[m], b2);
            }
        }
        __syncthreads();
    }

#pragma unroll
    for (int m = 0; m < 8; m++) {
        const int t = t0 + tx + 32 * m;
        if (t < T_DATA) {
#pragma unroll
            for (int n = 0; n < 5; n++) {
                const int s = ty * 5 + n;
                g_S[(size_t)(2 * s + part) * TPA + (T_NO - 1) + t] = fold2(acc[m][n]);
            }
        }
    }
}

// ---------------- kernel 3: fused conv -> leaky -> 2-layer MLP -> root partial ----------------
// grid: (ceil(T/512), 20 subunits); 256 threads.
// conv: per-thread 8h x 4t packed accumulators, time-reversed kernel in smem (even/odd-tap halves).
#define TT 512
#define SK_OFF 0                 // 6400 floats: Krev [c][h][j]
#define SS_OFF 6400              // 2 * 712 window
#define X_OFF  0                 // phase B: sX [16][516]
#define W_OFF  8320              // phase B: 560 weight floats
#define SM_FLOATS 8880

__global__ void __launch_bounds__(256) k_conv(const float* __restrict__ ffw,
                                              const float* __restrict__ ffb,
                                              const float* __restrict__ ff2w,
                                              const float* __restrict__ ff2b,
                                              const float* __restrict__ rootw) {
    const int s   = blockIdx.y;
    const int t0  = blockIdx.x * TT;
    const int tid = threadIdx.x;
    const int hg  = tid >> 7;          // 0/1 -> h in [hg*8, hg*8+8)
    const int tx  = tid & 127;

    __shared__ __align__(16) float smem[SM_FLOATS];

    // ---- load time-reversed kernel: smem[(c*16+h)*200 + j] = K[o][c][199-j]
    for (int idx = tid; idx < 6400; idx += 256) {
        const int c = idx / 3200;
        const int rem = idx % 3200;
        const int h = rem / 200;
        const int j = rem % 200;
        smem[SK_OFF + (c * 16 + h) * 200 + j] = g_K[(s * 16 + h) * 400 + c * 200 + (199 - j)];
    }
    // ---- load signal window: 2 channels x 711 samples
    for (int idx = tid; idx < 2 * 711; idx += 256) {
        const int c = idx / 711;
        const int j = idx % 711;
        smem[SS_OFF + c * 712 + j] = g_S[(size_t)(2 * s + c) * TPA + t0 + j];
    }
    __syncthreads();

    ull acc[8][4];
#pragma unroll
    for (int m = 0; m < 8; m++)
#pragma unroll
        for (int n = 0; n < 4; n++) acc[m][n] = 0ull;

#pragma unroll
    for (int c = 0; c < 2; c++) {
        const float* __restrict__ Sw = &smem[SS_OFF + c * 712];
        const float* __restrict__ Kc = &smem[SK_OFF + (c * 16 + hg * 8) * 200];
#pragma unroll 2
        for (int jj = 0; jj < 100; jj++) {
            ull a2[8];
#pragma unroll
            for (int m = 0; m < 8; m++)
                a2[m] = *(const ull*)&Kc[m * 200 + 2 * jj];
#pragma unroll
            for (int n = 0; n < 4; n++) {
                const int p = tx + 128 * n + 2 * jj;
                const ull b2 = pack2(Sw[p], Sw[p + 1]);
#pragma unroll
                for (int m = 0; m < 8; m++) fma2(acc[m][n], a2[m], b2);
            }
        }
    }
    __syncthreads();   // done reading sK/sS; smem is reused below

    // ---- conv_out + leakyReLU into smem as sX[h][t_local] (stride 516)
#pragma unroll
    for (int m = 0; m < 8; m++)
#pragma unroll
        for (int n = 0; n < 4; n++)
            smem[X_OFF + (hg * 8 + m) * 516 + tx + 128 * n] = leaky(fold2(acc[m][n]));

    // ---- load MLP weights: w1(256) b1(16) w2(256) b2(16) rw(16)
    for (int idx = tid; idx < 560; idx += 256) {
        float v;
        if (idx < 256)      v = ffw [s * 256 + idx];
        else if (idx < 272) v = ffb [s * 16  + idx - 256];
        else if (idx < 528) v = ff2w[s * 256 + idx - 272];
        else if (idx < 544) v = ff2b[s * 16  + idx - 528];
        else                v = rootw[s * 16 + idx - 544];
        smem[W_OFF + idx] = v;
    }
    __syncthreads();

    // ---- per-thread MLP for two t's (tid and tid+256), packed over the pair
    float xa[16], xb[16];
#pragma unroll
    for (int i = 0; i < 16; i++) {
        xa[i] = smem[X_OFF + i * 516 + tid];
        xb[i] = smem[X_OFF + i * 516 + tid + 256];
    }
    // layer 1
    {
        ull h[16];
#pragma unroll
        for (int o = 0; o < 16; o++) {
            const float b = smem[W_OFF + 256 + o];
            h[o] = pack2(b, b);
        }
#pragma unroll
        for (int i = 0; i < 16; i++) {
            const ull x2 = pack2(xa[i], xb[i]);
#pragma unroll
            for (int o = 0; o < 16; o++) {
                const float w = smem[W_OFF + o * 16 + i];
                fma2(h[o], pack2(w, w), x2);
            }
        }
#pragma unroll
        for (int o = 0; o < 16; o++) {
            float lo, hi;
            asm("mov.b64 {%0,%1}, %2;" : "=f"(lo), "=f"(hi) : "l"(h[o]));
            xa[o] = leaky(lo);
            xb[o] = leaky(hi);
        }
    }
    // layer 2
    {
        ull h[16];
#pragma unroll
        for (int o = 0; o < 16; o++) {
            const float b = smem[W_OFF + 528 + o];
            h[o] = pack2(b, b);
        }
#pragma unroll
        for (int i = 0; i < 16; i++) {
            const ull x2 = pack2(xa[i], xb[i]);
#pragma unroll
            for (int o = 0; o < 16; o++) {
                const float w = smem[W_OFF + 272 + o * 16 + i];
                fma2(h[o], pack2(w, w), x2);
            }
        }
#pragma unroll
        for (int o = 0; o < 16; o++) {
            float lo, hi;
            asm("mov.b64 {%0,%1}, %2;" : "=f"(lo), "=f"(hi) : "l"(h[o]));
            xa[o] = leaky(lo);
            xb[o] = leaky(hi);
        }
    }
    // root partial
    float ra = 0.f, rb = 0.f;
#pragma unroll
    for (int h = 0; h < 16; h++) {
        const float rw = smem[W_OFF + 544 + h];
        ra += rw * xa[h];
        rb += rw * xb[h];
    }
    const int ta = t0 + tid, tb = t0 + tid + 256;
    if (ta < T_DATA) g_P[s * T_DATA + ta] = ra;
    if (tb < T_DATA) g_P[s * T_DATA + tb] = rb;
}

// ---------------- kernel 4: reduce subunit partials + bias ----------------
__global__ void k_final(float* __restrict__ out,
                        const float* __restrict__ rootb,
                        const float* __restrict__ Vo) {
    const int t = blockIdx.x * 256 + threadIdx.x;
    if (t >= T_DATA) return;
    float a = rootb[0] + Vo[0];
#pragma unroll
    for (int s = 0; s < SUB_NO; s++) a += g_P[s * T_DATA + t];
    out[t] = a;
}

// ---------------- launch ----------------
extern "C" void kernel_launch(void* const* d_in, const int* in_sizes, int n_in,
                              void* d_out, int out_size) {
    const float* Se   = (const float*)d_in[0];
    const float* Si   = (const float*)d_in[1];
    const float* Ce   = (const float*)d_in[2];
    const float* Ci   = (const float*)d_in[3];
    const float* Wc   = (const float*)d_in[4];
    const float* ffw  = (const float*)d_in[5];
    const float* ffb  = (const float*)d_in[6];
    const float* ff2w = (const float*)d_in[7];
    const float* ff2b = (const float*)d_in[8];
    const float* rw   = (const float*)d_in[9];
    const float* rb   = (const float*)d_in[10];
    const float* Vo   = (const float*)d_in[11];
    float* out = (float*)d_out;

    k_zero<<<512, 256>>>();
    k_kern<<<640, 200>>>(Wc, out, out_size);
    {
        dim3 g((T_DATA + 255) / 256, 2);
        k_group<<<g, 128>>>(Se, Si, Ce, Ci);
    }
    {
        dim3 g((T_DATA + TT - 1) / TT, SUB_NO);
        k_conv<<<g, 256>>>(ffw, ffb, ff2w, ff2b, rw);
    }
    k_final<<<(T_DATA + 255) / 256, 256>>>(out, rb, Vo);
}

// round 3
// speedup vs baseline: 1.1923x; 1.1923x over previous
#include <cuda_runtime.h>

#define T_DATA 50000
#define SUB_NO 20
#define H_NO   16
#define T_NO   200
#define COS_NO 20
#define E_NO   1000
#define I_NO   200

#define PI_F 3.14159265358979f

// padded grouped-signal length per channel: 199 leading zeros + T + tail zeros
#define TPA (T_NO - 1 + T_DATA + 640)   // 50839

// ---------------- device scratch (static, no allocations) ----------------
__device__ float g_K[SUB_NO * H_NO * 2 * T_NO];   // K[o][c][tau], o = s*16+h
__device__ float g_S[2 * SUB_NO * TPA];           // 40 channels, channel-major
__device__ float g_P[SUB_NO * T_DATA];            // per-subunit root partials

// ---------------- packed f32x2 helpers ----------------
typedef unsigned long long ull;

__device__ __forceinline__ void fma2(ull &d, ull a, ull b) {
    asm("fma.rn.f32x2 %0, %1, %2, %0;" : "+l"(d) : "l"(a), "l"(b));
}
__device__ __forceinline__ ull pack2(float lo, float hi) {
    ull r;
    asm("mov.b64 %0, {%1,%2};" : "=l"(r) : "f"(lo), "f"(hi));
    return r;
}
__device__ __forceinline__ float fold2(ull v) {
    float lo, hi;
    asm("mov.b64 {%0,%1}, %2;" : "=f"(lo), "=f"(hi) : "l"(v));
    return lo + hi;
}
__device__ __forceinline__ float leaky(float v) { return v > 0.f ? v : 0.01f * v; }

// ---------------- cp.async helpers ----------------
__device__ __forceinline__ void cpa8(unsigned saddr, const void* gptr, int srcsz) {
    asm volatile("cp.async.ca.shared.global [%0], [%1], 8, %2;\n"
                 :: "r"(saddr), "l"(gptr), "r"(srcsz));
}
__device__ __forceinline__ void cpa_commit() { asm volatile("cp.async.commit_group;\n" ::); }
template<int N> __device__ __forceinline__ void cpa_wait() {
    asm volatile("cp.async.wait_group %0;\n" :: "n"(N));
}

// ---------------- kernel 0: zero ONLY the pad regions of g_S ----------------
// per channel: 199 leading + 640 trailing zeros = 839 pad elements
__global__ void k_zero() {
    const int n = 40 * 839;
    for (int i = blockIdx.x * blockDim.x + threadIdx.x; i < n; i += gridDim.x * blockDim.x) {
        const int ch = i / 839, p = i % 839;
        const int off = (p < 199) ? p : (T_NO - 1 + T_DATA + (p - 199));
        g_S[(size_t)ch * TPA + off] = 0.f;
    }
}

// ---------------- kernel 1: temporal kernels from raised-cosine basis ----------------
__global__ void k_kern(const float* __restrict__ Wc, float* __restrict__ out, int out_size) {
    const int oc  = blockIdx.x;        // 0..639
    const int ch  = oc & 1;
    const int od  = oc >> 1;           // 0..319
    const int tau = threadIdx.x;       // 0..199
    const float raw = 5.0f * logf((float)tau + 1.0f);
    float acc = 0.f;
#pragma unroll
    for (int b = 0; b < COS_NO; b++) {
        const float phi = 1.57079632679f * (float)b;
        float v = 0.f;
        if (raw >= phi - PI_F && raw <= phi + PI_F)
            v = 0.5f * cosf(raw - phi) + 0.5f;
        acc += v * Wc[od * (2 * COS_NO) + ch * COS_NO + b];
    }
    g_K[od * 400 + ch * 200 + tau] = acc;
    if (out_size >= T_DATA + 320 * 400)
        out[T_DATA + od * 400 + ch * 200 + (T_NO - 1 - tau)] = acc;
}

// ---------------- kernel 2: synapse grouping GEMMs (double-buffered cp.async) ----------------
#define GA_FLOATS (256 * 42)                // 10752 per stage
#define GB_OFF    (2 * GA_FLOATS)           // 21504
#define GB_FLOATS (20 * 42)                 // 840 per stage
#define GROUP_SMEM_FLOATS (GB_OFF + 2 * GB_FLOATS)   // 23184 -> 92736 B

__global__ void __launch_bounds__(128) k_group(const float* __restrict__ Se,
                                               const float* __restrict__ Si,
                                               const float* __restrict__ Ce,
                                               const float* __restrict__ Ci) {
    extern __shared__ float sm[];
    const unsigned sbase = (unsigned)__cvta_generic_to_shared(sm);

    const int part = blockIdx.y;
    const float* __restrict__ A = part ? Si : Se;
    const float* __restrict__ C = part ? Ci : Ce;
    const int Kdim = part ? I_NO : E_NO;
    const int nk0  = Kdim / 40;

    const int t0  = blockIdx.x * 256;
    const int tid = threadIdx.x;
    const int tx  = tid & 31;
    const int ty  = tid >> 5;          // 0..3 -> 5 subunits each

    ull acc[8][5];
#pragma unroll
    for (int m = 0; m < 8; m++)
#pragma unroll
        for (int n = 0; n < 5; n++) acc[m][n] = 0ull;

    // prefetch of one K-step tile into stage st
    auto prefetch = [&](int i, int st) {
        const int k0 = i * 40;
        for (int idx = tid; idx < 256 * 20; idx += 128) {
            const int r = idx / 20, c2 = idx % 20;
            const int t = t0 + r;
            const int tc = (t < T_DATA) ? t : (T_DATA - 1);   // clamp addr; zfill masks data
            cpa8(sbase + (unsigned)(st * GA_FLOATS + r * 42 + 2 * c2) * 4u,
                 &A[(size_t)tc * Kdim + k0 + 2 * c2], (t < T_DATA) ? 8 : 0);
        }
        for (int idx = tid; idx < 20 * 20; idx += 128) {
            const int r = idx / 20, c2 = idx % 20;
            cpa8(sbase + (unsigned)(GB_OFF + st * GB_FLOATS + r * 42 + 2 * c2) * 4u,
                 &C[(size_t)r * Kdim + k0 + 2 * c2], 8);
        }
    };

    prefetch(0, 0);
    cpa_commit();

    for (int i = 0; i < nk0; i++) {
        const int st = i & 1;
        if (i + 1 < nk0) prefetch(i + 1, st ^ 1);
        cpa_commit();
        cpa_wait<1>();
        __syncthreads();

        const float* sA = sm + st * GA_FLOATS;
        const float* sB = sm + GB_OFF + st * GB_FLOATS;
#pragma unroll 4
        for (int kk = 0; kk < 20; kk++) {
            ull a2[8];
#pragma unroll
            for (int m = 0; m < 8; m++)
                a2[m] = *(const ull*)&sA[(tx + 32 * m) * 42 + 2 * kk];
#pragma unroll
            for (int n = 0; n < 5; n++) {
                const ull b2 = *(const ull*)&sB[(ty * 5 + n) * 42 + 2 * kk];
#pragma unroll
                for (int m = 0; m < 8; m++) fma2(acc[m][n], a2[m], b2);
            }
        }
        __syncthreads();
    }

#pragma unroll
    for (int m = 0; m < 8; m++) {
        const int t = t0 + tx + 32 * m;
        if (t < T_DATA) {
#pragma unroll
            for (int n = 0; n < 5; n++) {
                const int s = ty * 5 + n;
                g_S[(size_t)(2 * s + part) * TPA + (T_NO - 1) + t] = fold2(acc[m][n]);
            }
        }
    }
}

// ---------------- kernel 3: fused conv -> leaky -> MLP -> root partial ----------------
// 512 threads, TT=1024 t per block. Thread: 4 h x 4 t-bases x 2 adjacent outputs.
// Even outputs: tap-pairs (KR[2j],KR[2j+1]) * aligned signal pair.
// Odd outputs:  shifted tap-pairs KO[j]=KR[j+1] * the NEXT aligned signal pair
//               (register-slid from the even stream) + scalar KR[0] fixup.
#define TT 1024
#define CTHREADS 512
#define KE_OFF 0          // 6400 floats
#define KO_OFF 6400       // 6400 floats
#define SW_OFF 12800      // 2 x 1224 floats
#define XS 1028           // sX row stride
#define XW_OFF 16448      // 560 weight floats (never overlaps phase A: 15248)
#define CONV_SMEM_FLOATS 17024   // 68096 bytes

__global__ void __launch_bounds__(CTHREADS, 1) k_conv(const float* __restrict__ ffw,
                                                      const float* __restrict__ ffb,
                                                      const float* __restrict__ ff2w,
                                                      const float* __restrict__ ff2b,
                                                      const float* __restrict__ rootw) {
    extern __shared__ float sm[];
    const int s   = blockIdx.y;
    const int t0  = blockIdx.x * TT;
    const int tid = threadIdx.x;
    const int tg  = tid >> 7;          // 0..3 -> h in [tg*4, tg*4+4)
    const int tx  = tid & 127;

    // ---- phase A loads: KR (time-reversed), KO (shifted), signal window, weights
    for (int idx = tid; idx < 6400; idx += CTHREADS) {
        const int c = idx / 3200;
        const int rem = idx % 3200;
        const int h = rem / 200;
        const int j = rem % 200;
        const float* gk = &g_K[(s * 16 + h) * 400 + c * 200];
        sm[KE_OFF + idx] = gk[199 - j];                       // KR[j] = K[199-j]
        sm[KO_OFF + idx] = (j < 199) ? gk[198 - j] : 0.f;     // KO[j] = KR[j+1], KR[200]=0
    }
    for (int idx = tid; idx < 2 * 1224; idx += CTHREADS) {
        const int c = idx / 1224;
        const int x = idx % 1224;
        sm[SW_OFF + idx] = g_S[(size_t)(2 * s + c) * TPA + t0 + x];
    }
    for (int idx = tid; idx < 560; idx += CTHREADS) {
        float v;
        if (idx < 256)      v = ffw [s * 256 + idx];
        else if (idx < 272) v = ffb [s * 16  + idx - 256];
        else if (idx < 528) v = ff2w[s * 256 + idx - 272];
        else if (idx < 544) v = ff2b[s * 16  + idx - 528];
        else                v = rootw[s * 16 + idx - 544];
        sm[XW_OFF + idx] = v;
    }
    __syncthreads();

    int tb[4];
#pragma unroll
    for (int n = 0; n < 4; n++) tb[n] = 2 * tx + 256 * n;

    ull accE[4][4], accO[4][4];
#pragma unroll
    for (int m = 0; m < 4; m++)
#pragma unroll
        for (int n = 0; n < 4; n++) { accE[m][n] = 0ull; accO[m][n] = 0ull; }

#pragma unroll
    for (int c = 0; c < 2; c++) {
        const float* __restrict__ KE = &sm[KE_OFF + c * 3200 + tg * 4 * 200];
        const float* __restrict__ KO = &sm[KO_OFF + c * 3200 + tg * 4 * 200];
        const float* __restrict__ Sb = &sm[SW_OFF + c * 1224];

        ull P[4];
#pragma unroll
        for (int n = 0; n < 4; n++) P[n] = *(const ull*)&Sb[tb[n]];

#pragma unroll 2
        for (int jj = 0; jj < 100; jj++) {
            ull kE[4], kO[4];
#pragma unroll
            for (int m = 0; m < 4; m++) {
                kE[m] = *(const ull*)&KE[m * 200 + 2 * jj];
                kO[m] = *(const ull*)&KO[m * 200 + 2 * jj];
            }
            ull Pn[4];
#pragma unroll
            for (int n = 0; n < 4; n++) Pn[n] = *(const ull*)&Sb[tb[n] + 2 * jj + 2];
#pragma unroll
            for (int n = 0; n < 4; n++)
#pragma unroll
                for (int m = 0; m < 4; m++) fma2(accE[m][n], kE[m], P[n]);
#pragma unroll
            for (int n = 0; n < 4; n++)
#pragma unroll
                for (int m = 0; m < 4; m++) fma2(accO[m][n], kO[m], Pn[n]);
#pragma unroll
            for (int n = 0; n < 4; n++) P[n] = Pn[n];
        }
    }

    // ---- fold + odd-output fixup (reads phase-A smem: do BEFORE the sync)
    float xE[4][4], xO[4][4];
#pragma unroll
    for (int m = 0; m < 4; m++) {
        const float kr0_0 = sm[KE_OFF + 0 * 3200 + (tg * 4 + m) * 200];
        const float kr0_1 = sm[KE_OFF + 1 * 3200 + (tg * 4 + m) * 200];
#pragma unroll
        for (int n = 0; n < 4; n++) {
            float e = fold2(accE[m][n]);
            float o = fold2(accO[m][n]);
            o += kr0_0 * sm[SW_OFF + 0 * 1224 + tb[n] + 1];
            o += kr0_1 * sm[SW_OFF + 1 * 1224 + tb[n] + 1];
            xE[m][n] = leaky(e);
            xO[m][n] = leaky(o);
        }
    }
    __syncthreads();

    // ---- write conv_out tile sX[h][t_local] as packed pairs
#pragma unroll
    for (int m = 0; m < 4; m++) {
        const int h = tg * 4 + m;
#pragma unroll
        for (int n = 0; n < 4; n++)
            *(ull*)&sm[h * XS + tb[n]] = pack2(xE[m][n], xO[m][n]);
    }
    __syncthreads();

    // ---- per-thread MLP for two t's (tid and tid+512), packed over the pair
    float xa[16], xb[16];
#pragma unroll
    for (int i = 0; i < 16; i++) {
        xa[i] = sm[i * XS + tid];
        xb[i] = sm[i * XS + tid + 512];
    }
    // layer 1
    {
        ull h[16];
#pragma unroll
        for (int o = 0; o < 16; o++) {
            const float b = sm[XW_OFF + 256 + o];
            h[o] = pack2(b, b);
        }
#pragma unroll
        for (int i = 0; i < 16; i++) {
            const ull x2 = pack2(xa[i], xb[i]);
#pragma unroll
            for (int o = 0; o < 16; o++) {
                const float w = sm[XW_OFF + o * 16 + i];
                fma2(h[o], pack2(w, w), x2);
            }
        }
#pragma unroll
        for (int o = 0; o < 16; o++) {
            float lo, hi;
            asm("mov.b64 {%0,%1}, %2;" : "=f"(lo), "=f"(hi) : "l"(h[o]));
            xa[o] = leaky(lo);
            xb[o] = leaky(hi);
        }
    }
    // layer 2
    {
        ull h[16];
#pragma unroll
        for (int o = 0; o < 16; o++) {
            const float b = sm[XW_OFF + 528 + o];
            h[o] = pack2(b, b);
        }
#pragma unroll
        for (int i = 0; i < 16; i++) {
            const ull x2 = pack2(xa[i], xb[i]);
#pragma unroll
            for (int o = 0; o < 16; o++) {
                const float w = sm[XW_OFF + 272 + o * 16 + i];
                fma2(h[o], pack2(w, w), x2);
            }
        }
#pragma unroll
        for (int o = 0; o < 16; o++) {
            float lo, hi;
            asm("mov.b64 {%0,%1}, %2;" : "=f"(lo), "=f"(hi) : "l"(h[o]));
            xa[o] = leaky(lo);
            xb[o] = leaky(hi);
        }
    }
    // root partial
    float ra = 0.f, rb = 0.f;
#pragma unroll
    for (int h = 0; h < 16; h++) {
        const float rw = sm[XW_OFF + 544 + h];
        ra += rw * xa[h];
        rb += rw * xb[h];
    }
    const int ta = t0 + tid, tbb = t0 + tid + 512;
    if (ta  < T_DATA) g_P[s * T_DATA + ta ] = ra;
    if (tbb < T_DATA) g_P[s * T_DATA + tbb] = rb;
}

// ---------------- kernel 4: reduce subunit partials + bias ----------------
__global__ void k_final(float* __restrict__ out,
                        const float* __restrict__ rootb,
                        const float* __restrict__ Vo) {
    const int t = blockIdx.x * 256 + threadIdx.x;
    if (t >= T_DATA) return;
    float a = rootb[0] + Vo[0];
#pragma unroll
    for (int s = 0; s < SUB_NO; s++) a += g_P[s * T_DATA + t];
    out[t] = a;
}

// ---------------- launch ----------------
extern "C" void kernel_launch(void* const* d_in, const int* in_sizes, int n_in,
                              void* d_out, int out_size) {
    const float* Se   = (const float*)d_in[0];
    const float* Si   = (const float*)d_in[1];
    const float* Ce   = (const float*)d_in[2];
    const float* Ci   = (const float*)d_in[3];
    const float* Wc   = (const float*)d_in[4];
    const float* ffw  = (const float*)d_in[5];
    const float* ffb  = (const float*)d_in[6];
    const float* ff2w = (const float*)d_in[7];
    const float* ff2b = (const float*)d_in[8];
    const float* rw   = (const float*)d_in[9];
    const float* rb   = (const float*)d_in[10];
    const float* Vo   = (const float*)d_in[11];
    float* out = (float*)d_out;

    cudaFuncSetAttribute(k_group, cudaFuncAttributeMaxDynamicSharedMemorySize,
                         GROUP_SMEM_FLOATS * 4);
    cudaFuncSetAttribute(k_conv, cudaFuncAttributeMaxDynamicSharedMemorySize,
                         CONV_SMEM_FLOATS * 4);

    k_zero<<<66, 512>>>();
    k_kern<<<640, 200>>>(Wc, out, out_size);
    {
        dim3 g((T_DATA + 255) / 256, 2);
        k_group<<<g, 128, GROUP_SMEM_FLOATS * 4>>>(Se, Si, Ce, Ci);
    }
    {
        dim3 g((T_DATA + TT - 1) / TT, SUB_NO);
        k_conv<<<g, CTHREADS, CONV_SMEM_FLOATS * 4>>>(ffw, ffb, ff2w, ff2b, rw);
    }
    k_final<<<(T_DATA + 255) / 256, 256>>>(out, rb, Vo);
}